// round 13
// baseline (speedup 1.0000x reference)
#include <cuda_runtime.h>
#include <cuda_bf16.h>
#include <stdint.h>

// GCN mean aggregation (converged design — at the L2 random-gather wall):
//   out[i, :] = mean over {nodes[i]} ∪ neigh_idx[i,0..31] of features[idx, :]
// features [V=100000, D=128] f32, nodes [B] int{32|64}, neigh [B,32] int{32|64}.
//
// Design history: evict_last residency split 80.9->47.6us; block=512 geometry
// 47.6->45.5us (block-size scan: 256/1024 -> 47.6, 512 -> 45.5).
// R13: persistent grid-stride at block=512 — 592 resident CTAs (148 SM x 4),
// zero wave transitions, prologue (dtype probe + policy) amortized over ~84
// nodes per warp instead of 1.
//  - warp per node; lane loads 4B -> one 128B line per LDG, 4 per 512B row
//  - feature loads: .nc + L2::evict_last (keep 51.2MB table L2-resident)
//  - index loads / output stores: streaming (.cs)
//  - dtype probe (int64 vs JAX-demoted int32): odd words of first 64 all
//    zero <=> little-endian int64.

static constexpr int KN = 32;
static constexpr float INV_CNT = 1.0f / 33.0f;

__device__ __forceinline__ uint64_t make_keep_policy() {
    uint64_t pol;
    asm("createpolicy.fractional.L2::evict_last.b64 %0, 1.0;" : "=l"(pol));
    return pol;
}

__device__ __forceinline__ float ldg_keep1(const float* p, uint64_t pol) {
    float v;
    asm volatile("ld.global.nc.L2::cache_hint.f32 %0, [%1], %2;"
                 : "=f"(v) : "l"(p), "l"(pol));
    return v;
}

__device__ __forceinline__ void stg_stream1(float* p, float v) {
    asm volatile("st.global.cs.f32 [%0], %1;" :: "l"(p), "f"(v) : "memory");
}

__device__ __forceinline__ int2 ldg_cs32x2(const int* p) {
    int2 v;
    asm volatile("ld.global.cs.v2.s32 {%0,%1}, [%2];"
                 : "=r"(v.x), "=r"(v.y) : "l"(p));
    return v;
}

__device__ __forceinline__ long long ldg_cs64(const long long* p) {
    long long v;
    asm volatile("ld.global.cs.s64 %0, [%1];" : "=l"(v) : "l"(p));
    return v;
}

__device__ __forceinline__ int ldg_cs32(const int* p) {
    int v;
    asm volatile("ld.global.cs.s32 %0, [%1];" : "=r"(v) : "l"(p));
    return v;
}

__global__ __launch_bounds__(512) void gcn_agg_kernel(
    const float* __restrict__ feat,
    const void*  __restrict__ nodes,
    const void*  __restrict__ neigh,
    float*       __restrict__ out,
    int B)
{
    const int lane  = threadIdx.x & 31;
    const int warp0 = (blockIdx.x * blockDim.x + threadIdx.x) >> 5;
    const int nwarp = (gridDim.x * blockDim.x) >> 5;

    const uint64_t pol = make_keep_policy();

    // Dtype probe once per warp: lanes 0-15 cover the first 64 int32 words
    // of neigh; odd words all zero <=> little-endian int64.
    int odd_ok = 1;
    if (lane < 16) {
        const int2 probe = ldg_cs32x2((const int*)neigh + 2 * lane);
        odd_ok = (probe.y == 0);
    }
    const bool is64 = (__ballot_sync(0xffffffffu, odd_ok) == 0xffffffffu);

    for (int node = warp0; node < B; node += nwarp) {
        // Lane j holds neighbor j (coalesced index fetch).
        int my_idx, self_idx;
        if (is64) {
            my_idx   = (int)ldg_cs64((const long long*)neigh + (long long)node * KN + lane);
            self_idx = (int)ldg_cs64((const long long*)nodes + node);
        } else {
            my_idx   = ldg_cs32((const int*)neigh + (long long)node * KN + lane);
            self_idx = ldg_cs32((const int*)nodes + node);
        }

        // Gather: 4 single-line LDG.32 per 512B row.
        float acc0, acc1, acc2, acc3;
        {
            const float* r = feat + (long long)self_idx * 128 + lane;
            acc0 = ldg_keep1(r,      pol);
            acc1 = ldg_keep1(r + 32, pol);
            acc2 = ldg_keep1(r + 64, pol);
            acc3 = ldg_keep1(r + 96, pol);
        }
#pragma unroll
        for (int j = 0; j < KN; j++) {
            const int idx = __shfl_sync(0xffffffffu, my_idx, j);
            const float* r = feat + (long long)idx * 128 + lane;
            acc0 += ldg_keep1(r,      pol);
            acc1 += ldg_keep1(r + 32, pol);
            acc2 += ldg_keep1(r + 64, pol);
            acc3 += ldg_keep1(r + 96, pol);
        }

        float* op = out + (long long)node * 128 + lane;
        stg_stream1(op,      acc0 * INV_CNT);
        stg_stream1(op + 32, acc1 * INV_CNT);
        stg_stream1(op + 64, acc2 * INV_CNT);
        stg_stream1(op + 96, acc3 * INV_CNT);
    }
}

extern "C" void kernel_launch(void* const* d_in, const int* in_sizes, int n_in,
                              void* d_out, int out_size) {
    const float* feat  = (const float*)d_in[0];
    const void*  nodes = d_in[1];
    const void*  neigh = d_in[2];
    float*       out   = (float*)d_out;

    const int B = in_sizes[1];  // 50000

    // Persistent: fill the chip exactly (148 SMs x 4 CTAs of 512 threads).
    const int threads = 512;
    const int blocks  = 148 * 4;
    gcn_agg_kernel<<<blocks, threads>>>(feat, nodes, neigh, out, B);
}

// round 14
// speedup vs baseline: 1.0942x; 1.0942x over previous
#include <cuda_runtime.h>
#include <cuda_bf16.h>
#include <stdint.h>

// GCN mean aggregation (FINAL converged design):
//   out[i, :] = mean over {nodes[i]} ∪ neigh_idx[i,0..31] of features[idx, :]
// features [V=100000, D=128] f32, nodes [B] int{32|64}, neigh [B,32] int{32|64}.
//
// Design history (12 structural variants benched):
//  - evict_last residency split for the 51.2MB table: 80.9 -> 47.6us (THE win)
//  - block-size scan: 256 -> 47.6, 512 -> 45.5, 1024 -> 47.6, persistent
//    grid-stride -> 51.6 (loop serialization kills cross-node MLP).
//    => 512-thread blocks, one node per warp.
//  - LDG width (32/128/256-bit), MLP 4-16, occupancy 44-91%, L1 bypass and
//    L2/DRAM splits are all FLAT: warm delivery ~19 TB/s = the chip's L2-hit
//    random-gather ceiling; traffic is irreducible (uniform random indices).
// R14 micro: int64 indices read via low-32-bit word only (values < 2^17),
// halving index-stream bytes.
//  - warp per node; lane loads 4B -> one 128B line per LDG, 4 per 512B row
//  - feature loads: .nc + L2::evict_last; index/output: streaming (.cs)
//  - dtype probe: odd words of neigh's first 64 words all zero <=> int64.

static constexpr int KN = 32;
static constexpr float INV_CNT = 1.0f / 33.0f;

__device__ __forceinline__ uint64_t make_keep_policy() {
    uint64_t pol;
    asm("createpolicy.fractional.L2::evict_last.b64 %0, 1.0;" : "=l"(pol));
    return pol;
}

__device__ __forceinline__ float ldg_keep1(const float* p, uint64_t pol) {
    float v;
    asm volatile("ld.global.nc.L2::cache_hint.f32 %0, [%1], %2;"
                 : "=f"(v) : "l"(p), "l"(pol));
    return v;
}

__device__ __forceinline__ void stg_stream1(float* p, float v) {
    asm volatile("st.global.cs.f32 [%0], %1;" :: "l"(p), "f"(v) : "memory");
}

__device__ __forceinline__ int2 ldg_cs32x2(const int* p) {
    int2 v;
    asm volatile("ld.global.cs.v2.s32 {%0,%1}, [%2];"
                 : "=r"(v.x), "=r"(v.y) : "l"(p));
    return v;
}

__device__ __forceinline__ int ldg_cs32(const int* p) {
    int v;
    asm volatile("ld.global.cs.s32 %0, [%1];" : "=r"(v) : "l"(p));
    return v;
}

__global__ __launch_bounds__(512) void gcn_agg_kernel(
    const float* __restrict__ feat,
    const void*  __restrict__ nodes,
    const void*  __restrict__ neigh,
    float*       __restrict__ out,
    int B)
{
    const int node = (blockIdx.x * blockDim.x + threadIdx.x) >> 5;
    const int lane = threadIdx.x & 31;
    if (node >= B) return;

    const uint64_t pol = make_keep_policy();

    // Dtype probe: lanes 0-15 cover the first 64 int32 words of neigh with
    // one v2 load each; odd words all zero <=> little-endian int64.
    int odd_ok = 1;
    if (lane < 16) {
        const int2 probe = ldg_cs32x2((const int*)neigh + 2 * lane);
        odd_ok = (probe.y == 0);
    }
    const bool is64 = (__ballot_sync(0xffffffffu, odd_ok) == 0xffffffffu);

    // Fetch this node's indices: lane j holds neighbor j. For int64 data,
    // read only the low 32-bit word of each 8B index (values < 2^31).
    int my_idx, self_idx;
    if (is64) {
        const int* n = (const int*)neigh;
        my_idx   = ldg_cs32(n + ((long long)node * KN + lane) * 2);
        self_idx = ldg_cs32((const int*)nodes + (long long)node * 2);
    } else {
        my_idx   = ldg_cs32((const int*)neigh + (long long)node * KN + lane);
        self_idx = ldg_cs32((const int*)nodes + node);
    }

    // Gather: 4 single-line LDG.32 per 512B row.
    float acc0, acc1, acc2, acc3;
    {
        const float* r = feat + (long long)self_idx * 128 + lane;
        acc0 = ldg_keep1(r,      pol);
        acc1 = ldg_keep1(r + 32, pol);
        acc2 = ldg_keep1(r + 64, pol);
        acc3 = ldg_keep1(r + 96, pol);
    }
#pragma unroll
    for (int j = 0; j < KN; j++) {
        const int idx = __shfl_sync(0xffffffffu, my_idx, j);
        const float* r = feat + (long long)idx * 128 + lane;
        acc0 += ldg_keep1(r,      pol);
        acc1 += ldg_keep1(r + 32, pol);
        acc2 += ldg_keep1(r + 64, pol);
        acc3 += ldg_keep1(r + 96, pol);
    }

    float* op = out + (long long)node * 128 + lane;
    stg_stream1(op,      acc0 * INV_CNT);
    stg_stream1(op + 32, acc1 * INV_CNT);
    stg_stream1(op + 64, acc2 * INV_CNT);
    stg_stream1(op + 96, acc3 * INV_CNT);
}

extern "C" void kernel_launch(void* const* d_in, const int* in_sizes, int n_in,
                              void* d_out, int out_size) {
    const float* feat  = (const float*)d_in[0];
    const void*  nodes = d_in[1];
    const void*  neigh = d_in[2];
    float*       out   = (float*)d_out;

    const int B = in_sizes[1];  // 50000

    const int threads = 512;   // 16 warps = 16 nodes per block (scan optimum)
    const int blocks  = (B * 32 + threads - 1) / threads;
    gcn_agg_kernel<<<blocks, threads>>>(feat, nodes, neigh, out, B);
}

// round 15
// speedup vs baseline: 1.0950x; 1.0007x over previous
#include <cuda_runtime.h>
#include <cuda_bf16.h>
#include <stdint.h>

// GCN mean aggregation (R11 exact reproduction — best observed: 45.5us):
//   out[i, :] = mean over {nodes[i]} ∪ neigh_idx[i,0..31] of features[idx, :]
// features [V=100000, D=128] f32, nodes [B] int{32|64}, neigh [B,32] int{32|64}.
//
// Design validated over 13 variants:
//  - warp per node; lane loads 4B -> each LDG touches exactly one 128B line,
//    4 loads per 512B feature row, fully coalesced
//  - feature loads: .nc + L2::evict_last policy (THE win, 80.9 -> 47.6us:
//    keeps the 51.2MB table resident against write-once stream eviction)
//  - index loads / output stores: streaming (.cs)
//  - indices fetched coalesced (lane j = neighbor j) + shfl broadcast
//  - dtype probe (int64 vs JAX-demoted int32): lanes 0-15, one v2 load each;
//    little-endian int64 values < 2^31 have every odd 32-bit word zero
//  - block-size scan: 256 -> 47.6, 512 -> 45.5, 1024 -> 47.6,
//    persistent grid-stride -> 51.6. 512 is the optimum.
// This round: byte-exact R11 re-bench to confirm 45.5 reproducibility
// (R14's "free" micro-diffs — hoisted policy + stride-8 low-word int64
// loads — regressed to 47.2; reverted).

static constexpr int KN = 32;
static constexpr float INV_CNT = 1.0f / 33.0f;

__device__ __forceinline__ uint64_t make_keep_policy() {
    uint64_t pol;
    asm("createpolicy.fractional.L2::evict_last.b64 %0, 1.0;" : "=l"(pol));
    return pol;
}

__device__ __forceinline__ float ldg_keep1(const float* p, uint64_t pol) {
    float v;
    asm volatile("ld.global.nc.L2::cache_hint.f32 %0, [%1], %2;"
                 : "=f"(v) : "l"(p), "l"(pol));
    return v;
}

__device__ __forceinline__ void stg_stream1(float* p, float v) {
    asm volatile("st.global.cs.f32 [%0], %1;" :: "l"(p), "f"(v) : "memory");
}

__device__ __forceinline__ int2 ldg_cs32x2(const int* p) {
    int2 v;
    asm volatile("ld.global.cs.v2.s32 {%0,%1}, [%2];"
                 : "=r"(v.x), "=r"(v.y) : "l"(p));
    return v;
}

__device__ __forceinline__ long long ldg_cs64(const long long* p) {
    long long v;
    asm volatile("ld.global.cs.s64 %0, [%1];" : "=l"(v) : "l"(p));
    return v;
}

__device__ __forceinline__ int ldg_cs32(const int* p) {
    int v;
    asm volatile("ld.global.cs.s32 %0, [%1];" : "=r"(v) : "l"(p));
    return v;
}

__global__ __launch_bounds__(512) void gcn_agg_kernel(
    const float* __restrict__ feat,
    const void*  __restrict__ nodes,
    const void*  __restrict__ neigh,
    float*       __restrict__ out,
    int B)
{
    const int node = (blockIdx.x * blockDim.x + threadIdx.x) >> 5;
    const int lane = threadIdx.x & 31;
    if (node >= B) return;

    // Inline dtype probe: lanes 0-15 cover the first 64 int32 words of neigh
    // with one v2 load each; odd words all zero <=> little-endian int64.
    int odd_ok = 1;
    if (lane < 16) {
        const int2 probe = ldg_cs32x2((const int*)neigh + 2 * lane);
        odd_ok = (probe.y == 0);
    }
    const bool is64 = (__ballot_sync(0xffffffffu, odd_ok) == 0xffffffffu);

    // Fetch this node's indices: lane j holds neighbor j (coalesced).
    int my_idx, self_idx;
    if (is64) {
        my_idx   = (int)ldg_cs64((const long long*)neigh + (long long)node * KN + lane);
        self_idx = (int)ldg_cs64((const long long*)nodes + node);
    } else {
        my_idx   = ldg_cs32((const int*)neigh + (long long)node * KN + lane);
        self_idx = ldg_cs32((const int*)nodes + node);
    }

    const uint64_t pol = make_keep_policy();

    // Gather: 4 single-line LDG.32 per 512B row.
    float acc0, acc1, acc2, acc3;
    {
        const float* r = feat + (long long)self_idx * 128 + lane;
        acc0 = ldg_keep1(r,      pol);
        acc1 = ldg_keep1(r + 32, pol);
        acc2 = ldg_keep1(r + 64, pol);
        acc3 = ldg_keep1(r + 96, pol);
    }
#pragma unroll
    for (int j = 0; j < KN; j++) {
        const int idx = __shfl_sync(0xffffffffu, my_idx, j);
        const float* r = feat + (long long)idx * 128 + lane;
        acc0 += ldg_keep1(r,      pol);
        acc1 += ldg_keep1(r + 32, pol);
        acc2 += ldg_keep1(r + 64, pol);
        acc3 += ldg_keep1(r + 96, pol);
    }

    float* op = out + (long long)node * 128 + lane;
    stg_stream1(op,      acc0 * INV_CNT);
    stg_stream1(op + 32, acc1 * INV_CNT);
    stg_stream1(op + 64, acc2 * INV_CNT);
    stg_stream1(op + 96, acc3 * INV_CNT);
}

extern "C" void kernel_launch(void* const* d_in, const int* in_sizes, int n_in,
                              void* d_out, int out_size) {
    const float* feat  = (const float*)d_in[0];
    const void*  nodes = d_in[1];
    const void*  neigh = d_in[2];
    float*       out   = (float*)d_out;

    const int B = in_sizes[1];  // 50000

    const int threads = 512;   // 16 warps = 16 nodes per block (scan optimum)
    const int blocks  = (B * 32 + threads - 1) / threads;
    gcn_agg_kernel<<<blocks, threads>>>(feat, nodes, neigh, out, B);
}